// round 9
// baseline (speedup 1.0000x reference)
#include <cuda_runtime.h>
#include <cuda_bf16.h>
#include <math.h>
#include <stdint.h>

// ---------------------------------------------------------------------------
// GatedDeltaNetVarlen — round 9:
//   R8 chunked delta rule with the cp.async loader FIXED (cp16f = 16 BYTES):
//   each thread now loads 3x 4-float segments per chunk (full K/Q/V tiles).
//   GEMM / splits / conv / rmsnorm identical to R7 (proven).
// ---------------------------------------------------------------------------

#define TOTAL_MAX 1536
#define HIDDEN    1024
#define CONV_DIM  2048
#define KEY_DIM   512
#define VAL_DIM   1024
#define HV        16
#define GK        1024
#define SSTR      40     // GEMM smem row stride (bf16)

typedef __nv_bfloat16 bf16;
typedef unsigned long long ull;

__device__ float g_mixed[TOTAL_MAX * CONV_DIM];
__device__ float g_qkv  [TOTAL_MAX * CONV_DIM];
__device__ float g_z    [TOTAL_MAX * VAL_DIM];
__device__ float g_c3   [TOTAL_MAX * 128];
__device__ float g_beta [TOTAL_MAX * HV];
__device__ float g_gate [TOTAL_MAX * HV];
__device__ float g_o    [TOTAL_MAX * VAL_DIM];

__device__ bf16 g_hs_h  [TOTAL_MAX * HIDDEN];
__device__ bf16 g_hs_l  [TOTAL_MAX * HIDDEN];
__device__ bf16 g_wqkv_h[CONV_DIM * HIDDEN];
__device__ bf16 g_wqkv_l[CONV_DIM * HIDDEN];
__device__ bf16 g_wz_h  [VAL_DIM * HIDDEN];
__device__ bf16 g_wz_l  [VAL_DIM * HIDDEN];
__device__ bf16 g_wba_h [128 * HIDDEN];
__device__ bf16 g_wba_l [128 * HIDDEN];
__device__ bf16 g_wout_h[HIDDEN * VAL_DIM];
__device__ bf16 g_wout_l[HIDDEN * VAL_DIM];
__device__ bf16 g_on_h  [TOTAL_MAX * VAL_DIM];
__device__ bf16 g_on_l  [TOTAL_MAX * VAL_DIM];

// ---------------------------------------------------------------------------
// helpers
// ---------------------------------------------------------------------------
__device__ __forceinline__ void ldsm_x4(unsigned& r0, unsigned& r1, unsigned& r2, unsigned& r3,
                                        const bf16* p)
{
    unsigned addr = (unsigned)__cvta_generic_to_shared(p);
    asm volatile("ldmatrix.sync.aligned.m8n8.x4.shared.b16 {%0,%1,%2,%3}, [%4];"
                 : "=r"(r0), "=r"(r1), "=r"(r2), "=r"(r3) : "r"(addr));
}

__device__ __forceinline__ void mma16816(float* c, const unsigned* a, const unsigned* b)
{
    asm volatile(
        "mma.sync.aligned.m16n8k16.row.col.f32.bf16.bf16.f32 "
        "{%0,%1,%2,%3},{%4,%5,%6,%7},{%8,%9},{%0,%1,%2,%3};\n"
        : "+f"(c[0]), "+f"(c[1]), "+f"(c[2]), "+f"(c[3])
        : "r"(a[0]), "r"(a[1]), "r"(a[2]), "r"(a[3]), "r"(b[0]), "r"(b[1]));
}

// copies 16 BYTES (4 floats)
__device__ __forceinline__ void cp16f(const float* dst_smem, const float* src)
{
    unsigned d = (unsigned)__cvta_generic_to_shared(dst_smem);
    asm volatile("cp.async.cg.shared.global [%0], [%1], 16;" :: "r"(d), "l"(src));
}
__device__ __forceinline__ void cp4f(const float* dst_smem, const float* src)
{
    unsigned d = (unsigned)__cvta_generic_to_shared(dst_smem);
    asm volatile("cp.async.ca.shared.global [%0], [%1], 4;" :: "r"(d), "l"(src));
}
#define CP_COMMIT() asm volatile("cp.async.commit_group;")
template<int N> __device__ __forceinline__ void cp_wait() {
    asm volatile("cp.async.wait_group %0;" :: "n"(N));
}

// packed f32x2 ops (Blackwell)
__device__ __forceinline__ ull fma2(ull a, ull b, ull c) {
    ull d; asm("fma.rn.f32x2 %0, %1, %2, %3;" : "=l"(d) : "l"(a), "l"(b), "l"(c)); return d;
}
__device__ __forceinline__ ull mul2(ull a, ull b) {
    ull d; asm("mul.rn.f32x2 %0, %1, %2;" : "=l"(d) : "l"(a), "l"(b)); return d;
}
__device__ __forceinline__ ull add2(ull a, ull b) {
    ull d; asm("add.rn.f32x2 %0, %1, %2;" : "=l"(d) : "l"(a), "l"(b)); return d;
}
__device__ __forceinline__ ull pk2(float lo, float hi) {
    ull r; asm("mov.b64 %0, {%1,%2};" : "=l"(r) : "f"(lo), "f"(hi)); return r;
}
__device__ __forceinline__ float hsum2(ull p) {
    float lo, hi; asm("mov.b64 {%0,%1}, %2;" : "=f"(lo), "=f"(hi) : "l"(p));
    return lo + hi;
}

// ---------------------------------------------------------------------------
// bf16 split GEMM, triple N-range (proven R3/R6 kernel)
// ---------------------------------------------------------------------------
__global__ __launch_bounds__(256) void gemm_bf16split_tri(
    const bf16* __restrict__ Ah, const bf16* __restrict__ Al,
    const bf16* __restrict__ B1h, const bf16* __restrict__ B1l,
    const bf16* __restrict__ B2h, const bf16* __restrict__ B2l,
    const bf16* __restrict__ B3h, const bf16* __restrict__ B3l,
    float* __restrict__ C1, float* __restrict__ C2, float* __restrict__ C3,
    int N1, int N2, int N3)
{
    __shared__ bf16 As[2][128][SSTR];
    __shared__ bf16 Bs[2][128][SSTR];

    const int tid  = threadIdx.x;
    const int lane = tid & 31;
    const int wid  = tid >> 5;
    const int wm   = wid & 3;
    const int wn   = wid >> 2;
    const int bm   = blockIdx.y * 128;
    const int bnG  = blockIdx.x * 128;

    const bf16* Bh; const bf16* Bl; float* C; int bn, ldc;
    if (bnG < N1)           { Bh = B1h; Bl = B1l; C = C1; bn = bnG;           ldc = N1; }
    else if (bnG < N1 + N2) { Bh = B2h; Bl = B2l; C = C2; bn = bnG - N1;      ldc = N2; }
    else                    { Bh = B3h; Bl = B3l; C = C3; bn = bnG - N1 - N2; ldc = N3; }

    const int lrow = tid >> 2;
    const int lcol = (tid & 3) * 8;

    const bf16* APs[3] = { Ah, Al, Ah };
    const bf16* BPs[3] = { Bh, Bh, Bl };

    float c[2][8][4];
#pragma unroll
    for (int mi = 0; mi < 2; mi++)
#pragma unroll
        for (int ni = 0; ni < 8; ni++)
#pragma unroll
            for (int r = 0; r < 4; r++) c[mi][ni][r] = 0.f;

    const int NIT = 3 * (GK / 32);

    {
        uint4 pa0 = *(const uint4*)(APs[0] + (size_t)(bm + lrow) * GK + lcol);
        uint4 pa1 = *(const uint4*)(APs[0] + (size_t)(bm + lrow + 64) * GK + lcol);
        uint4 pb0 = *(const uint4*)(BPs[0] + (size_t)(bn + lrow) * GK + lcol);
        uint4 pb1 = *(const uint4*)(BPs[0] + (size_t)(bn + lrow + 64) * GK + lcol);
        *(uint4*)&As[0][lrow][lcol]      = pa0;
        *(uint4*)&As[0][lrow + 64][lcol] = pa1;
        *(uint4*)&Bs[0][lrow][lcol]      = pb0;
        *(uint4*)&Bs[0][lrow + 64][lcol] = pb1;
    }
    __syncthreads();

    const int lrow16 = lane & 15;
    const int lhalf  = lane >> 4;
    const int l8     = lane & 7;
    const int grp    = lane >> 3;

    for (int it = 0; it < NIT; ++it) {
        const int cur = it & 1;
        const bool has_next = (it + 1 < NIT);

        uint4 pa0, pa1, pb0, pb1;
        if (has_next) {
            const int nit = it + 1;
            const int p  = nit >> 5;
            const int k0 = (nit & 31) * 32;
            pa0 = *(const uint4*)(APs[p] + (size_t)(bm + lrow) * GK + k0 + lcol);
            pa1 = *(const uint4*)(APs[p] + (size_t)(bm + lrow + 64) * GK + k0 + lcol);
            pb0 = *(const uint4*)(BPs[p] + (size_t)(bn + lrow) * GK + k0 + lcol);
            pb1 = *(const uint4*)(BPs[p] + (size_t)(bn + lrow + 64) * GK + k0 + lcol);
        }

#pragma unroll
        for (int kk = 0; kk < 32; kk += 16) {
            unsigned a[2][4];
#pragma unroll
            for (int mi = 0; mi < 2; mi++)
                ldsm_x4(a[mi][0], a[mi][1], a[mi][2], a[mi][3],
                        &As[cur][wm * 32 + mi * 16 + lrow16][kk + 8 * lhalf]);
            unsigned b[8][2];
#pragma unroll
            for (int nj = 0; nj < 4; nj++)
                ldsm_x4(b[2 * nj][0], b[2 * nj][1], b[2 * nj + 1][0], b[2 * nj + 1][1],
                        &Bs[cur][wn * 64 + nj * 16 + (grp >> 1) * 8 + l8][kk + 8 * (grp & 1)]);
#pragma unroll
            for (int mi = 0; mi < 2; mi++)
#pragma unroll
                for (int ni = 0; ni < 8; ni++)
                    mma16816(c[mi][ni], a[mi], b[ni]);
        }

        if (has_next) {
            const int nxt = cur ^ 1;
            *(uint4*)&As[nxt][lrow][lcol]      = pa0;
            *(uint4*)&As[nxt][lrow + 64][lcol] = pa1;
            *(uint4*)&Bs[nxt][lrow][lcol]      = pb0;
            *(uint4*)&Bs[nxt][lrow + 64][lcol] = pb1;
            __syncthreads();
        }
    }

    const int g  = lane >> 2;
    const int t4 = lane & 3;
#pragma unroll
    for (int mi = 0; mi < 2; mi++) {
        const int row0 = bm + wm * 32 + mi * 16 + g;
#pragma unroll
        for (int ni = 0; ni < 8; ni++) {
            const int col = bn + wn * 64 + ni * 8 + 2 * t4;
            *(float2*)(C + (size_t)row0 * ldc + col)       = make_float2(c[mi][ni][0], c[mi][ni][1]);
            *(float2*)(C + (size_t)(row0 + 8) * ldc + col) = make_float2(c[mi][ni][2], c[mi][ni][3]);
        }
    }
}

// ---------------------------------------------------------------------------
// Vectorized fp32 -> (hi,lo) bf16 split
// ---------------------------------------------------------------------------
__device__ __forceinline__ void split_one4(float4 v, uint2* h, uint2* l, int i)
{
    bf16 h0 = __float2bfloat16(v.x), h1 = __float2bfloat16(v.y);
    bf16 h2 = __float2bfloat16(v.z), h3 = __float2bfloat16(v.w);
    bf16 l0 = __float2bfloat16(v.x - __bfloat162float(h0));
    bf16 l1 = __float2bfloat16(v.y - __bfloat162float(h1));
    bf16 l2 = __float2bfloat16(v.z - __bfloat162float(h2));
    bf16 l3 = __float2bfloat16(v.w - __bfloat162float(h3));
    uint2 hv, lv;
    hv.x = ((unsigned)__bfloat16_as_ushort(h1) << 16) | __bfloat16_as_ushort(h0);
    hv.y = ((unsigned)__bfloat16_as_ushort(h3) << 16) | __bfloat16_as_ushort(h2);
    lv.x = ((unsigned)__bfloat16_as_ushort(l1) << 16) | __bfloat16_as_ushort(l0);
    lv.y = ((unsigned)__bfloat16_as_ushort(l3) << 16) | __bfloat16_as_ushort(l2);
    h[i] = hv;
    l[i] = lv;
}

__global__ __launch_bounds__(256) void split4_kernel(
    const float4* __restrict__ x, uint2* __restrict__ h, uint2* __restrict__ l, int n4)
{
    int i = blockIdx.x * blockDim.x + threadIdx.x;
    if (i >= n4) return;
    split_one4(x[i], h, l, i);
}

#define NZ4  (VAL_DIM * HIDDEN / 4)
#define NO4  (HIDDEN * VAL_DIM / 4)
#define NBA4 (128 * HIDDEN / 4)
__global__ __launch_bounds__(256) void split_weights2_kernel(
    const float4* __restrict__ wz, const float4* __restrict__ wout,
    const float* __restrict__ Wb, const float* __restrict__ Wa,
    uint2* __restrict__ wzh, uint2* __restrict__ wzl,
    uint2* __restrict__ wouth, uint2* __restrict__ woutl,
    uint2* __restrict__ wbah, uint2* __restrict__ wbal)
{
    int i = blockIdx.x * blockDim.x + threadIdx.x;
    if (i < NZ4) {
        split_one4(wz[i], wzh, wzl, i);
    } else if (i < NZ4 + NO4) {
        int j = i - NZ4;
        split_one4(wout[j], wouth, woutl, j);
    } else if (i < NZ4 + NO4 + NBA4) {
        int j = i - NZ4 - NO4;
        int e = j * 4;
        float4 v;
        if (e < 16 * HIDDEN)      v = *(const float4*)(Wb + e);
        else if (e < 32 * HIDDEN) v = *(const float4*)(Wa + e - 16 * HIDDEN);
        else                      v = make_float4(0.f, 0.f, 0.f, 0.f);
        split_one4(v, wbah, wbal, j);
    }
}

__global__ __launch_bounds__(256) void ba_finish_kernel(
    const float* __restrict__ c3, const float* __restrict__ dtb,
    const float* __restrict__ Alog, float* __restrict__ beta, float* __restrict__ gate,
    int total)
{
    int idx = blockIdx.x * blockDim.x + threadIdx.x;
    int t = idx >> 5;
    int o = idx & 31;
    if (t >= total) return;
    float x = c3[(size_t)t * 128 + o];
    if (o < HV) {
        beta[(size_t)t * HV + o] = 1.f / (1.f + expf(-x));
    } else {
        int hh = o - HV;
        float xv = x + dtb[hh];
        float sp = (xv > 20.f) ? xv : log1pf(expf(xv));
        gate[(size_t)t * HV + hh] = -expf(Alog[hh]) * sp;
    }
}

// ---------------------------------------------------------------------------
// Fused causal depthwise conv(4) + silu + per-head q/k L2 norm
// ---------------------------------------------------------------------------
__global__ __launch_bounds__(256) void conv_norm_kernel(
    const float* __restrict__ mixed, const float* __restrict__ cw,
    const int* __restrict__ cu, int B, float* __restrict__ out)
{
    const int t = blockIdx.x;
    const int tid = threadIdx.x;
    const int c0 = tid * 8;

    int start = 0;
    for (int i = 1; i < B; i++) { int s = cu[i]; if (t >= s) start = s; }

    float y[8];
#pragma unroll
    for (int j = 0; j < 8; j++) {
        const int c = c0 + j;
        const float4 w4 = *(const float4*)(cw + c * 4);
        float acc = mixed[(size_t)t * CONV_DIM + c] * w4.w;
        if (t - 1 >= start) acc = fmaf(mixed[(size_t)(t - 1) * CONV_DIM + c], w4.z, acc);
        if (t - 2 >= start) acc = fmaf(mixed[(size_t)(t - 2) * CONV_DIM + c], w4.y, acc);
        if (t - 3 >= start) acc = fmaf(mixed[(size_t)(t - 3) * CONV_DIM + c], w4.x, acc);
        y[j] = acc / (1.f + expf(-acc));
    }

    if (c0 < 2 * KEY_DIM) {
        float ss = 0.f;
#pragma unroll
        for (int j = 0; j < 8; j++) ss = fmaf(y[j], y[j], ss);
        ss += __shfl_xor_sync(0xffffffffu, ss, 1);
        ss += __shfl_xor_sync(0xffffffffu, ss, 2);
        ss += __shfl_xor_sync(0xffffffffu, ss, 4);
        float r = rsqrtf(ss + 1e-6f);
        if (c0 < KEY_DIM) r *= 0.125f;
#pragma unroll
        for (int j = 0; j < 8; j++) y[j] *= r;
    }

    float4* dst = (float4*)(out + (size_t)t * CONV_DIM + c0);
    dst[0] = make_float4(y[0], y[1], y[2], y[3]);
    dst[1] = make_float4(y[4], y[5], y[6], y[7]);
}

// ---------------------------------------------------------------------------
// CHUNKED gated delta rule (C=16). One block per (seq,head), 256 threads.
// v = tid>>2 (value dim), kh = tid&3 (16 k-rows each).
// S2[p] packs S[kh*16+2p][v], S[kh*16+2p+1][v] as f32x2.
// ---------------------------------------------------------------------------
#define KPAD 68   // padded row stride (floats) for K/Q chunk tiles

__global__ __launch_bounds__(256) void recurrence_chunked(
    const float* __restrict__ qkv, const float* __restrict__ beta,
    const float* __restrict__ gate, const int* __restrict__ cu,
    float* __restrict__ O, int total)
{
    const int b = blockIdx.x >> 4;
    const int h = blockIdx.x & 15;
    const int start = cu[b];
    const int end   = cu[b + 1];

    const int tid = threadIdx.x;
    const int v  = tid >> 2;
    const int kh = tid & 3;

    const int qoff = (h >> 1) * 64;
    const int koff = KEY_DIM + (h >> 1) * 64;
    const int voff = 2 * KEY_DIM + h * 64;

    ull S2[8];
#pragma unroll
    for (int i = 0; i < 8; i++) S2[i] = 0ull;

    __shared__ __align__(16) float bK[2][16 * KPAD];
    __shared__ __align__(16) float bQ[2][16 * KPAD];
    __shared__ __align__(16) float bV[2][16 * 64];
    __shared__ float bg[2][16], bb[2][16];
    __shared__ float sKS0[16 * 64], sQS0[16 * 64];
    __shared__ float sKK[256], sQK[256], sM[256], sP[256];
    __shared__ float sA[16], sE15[16];

    // FIXED loader: cp16f copies 16 BYTES (4 floats).
    // Each thread: row i = tid>>4, segment seg = tid&15 (4 floats at seg*4).
    auto issue_chunk = [&](int t0, int s) {
        const int i  = tid >> 4;
        const int sg = (tid & 15) * 4;
        int ts = t0 + i; if (ts > total - 1) ts = total - 1;
        const float* __restrict__ row = qkv + (size_t)ts * CONV_DIM;
        cp16f(&bK[s][i * KPAD + sg], row + koff + sg);
        cp16f(&bQ[s][i * KPAD + sg], row + qoff + sg);
        cp16f(&bV[s][i * 64  + sg], row + voff + sg);
        if (tid < 16) {
            int tg = t0 + tid; if (tg > total - 1) tg = total - 1;
            cp4f(&bg[s][tid], gate + (size_t)tg * HV + h);
        } else if (tid < 32) {
            int tg = t0 + tid - 16; if (tg > total - 1) tg = total - 1;
            cp4f(&bb[s][tid - 16], beta + (size_t)tg * HV + h);
        }
    };

    const int nch = (end - start + 15) >> 4;
    issue_chunk(start, 0);
    CP_COMMIT();

    for (int ci = 0; ci < nch; ci++) {
        const int s  = ci & 1;
        const int t0 = start + ci * 16;
        const int len = (end - t0 < 16) ? (end - t0) : 16;

        cp_wait<0>();
        __syncthreads();
        if (ci + 1 < nch) issue_chunk(t0 + 16, s ^ 1);
        CP_COMMIT();

        const float* Km = bK[s];
        const float* Qm = bQ[s];
        const float* Vm = bV[s];

        // ---- region 1: pad fix, KS0/QS0 partials, KK/QK dots ----
        if (tid >= len && tid < 16) { bg[s][tid] = 0.f; bb[s][tid] = 0.f; }

#pragma unroll
        for (int t = 0; t < 16; t++) {
            const ulonglong2* kp = (const ulonglong2*)(Km + t * KPAD + kh * 16);
            const ulonglong2* qp = (const ulonglong2*)(Qm + t * KPAD + kh * 16);
            ulonglong2 k0 = kp[0], k1 = kp[1], k2 = kp[2], k3 = kp[3];
            ulonglong2 q0 = qp[0], q1 = qp[1], q2 = qp[2], q3 = qp[3];
            ull ak = 0, bk = 0, aq = 0, bq = 0;
            ak = fma2(k0.x, S2[0], ak); bk = fma2(k0.y, S2[1], bk);
            ak = fma2(k1.x, S2[2], ak); bk = fma2(k1.y, S2[3], bk);
            ak = fma2(k2.x, S2[4], ak); bk = fma2(k2.y, S2[5], bk);
            ak = fma2(k3.x, S2[6], ak); bk = fma2(k3.y, S2[7], bk);
            aq = fma2(q0.x, S2[0], aq); bq = fma2(q0.y, S2[1], bq);
            aq = fma2(q1.x, S2[2], aq); bq = fma2(q1.y, S2[3], bq);
            aq = fma2(q2.x, S2[4], aq); bq = fma2(q2.y, S2[5], bq);
            aq = fma2(q3.x, S2[6], aq); bq = fma2(q3.y, S2[7], bq);
            float pk = hsum2(add2(ak, bk));
            float pq = hsum2(add2(aq, bq));
            pk += __shfl_xor_sync(0xffffffffu, pk, 1);
            pq += __shfl_xor_sync(0xffffffffu, pq, 1);
            pk += __shfl_xor_sync(0xffffffffu, pk, 2);
            pq += __shfl_xor_sync(0xffffffffu, pq, 2);
            if (kh == 0) { sKS0[t * 64 + v] = pk; sQS0[t * 64 + v] = pq; }
        }

        {   // KK[t][j] = k_t.k_j ; QK[t][j] = q_t.k_j
            const int t = tid >> 4, j = tid & 15;
            const ulonglong2* ktp = (const ulonglong2*)(Km + t * KPAD);
            const ulonglong2* kjp = (const ulonglong2*)(Km + j * KPAD);
            const ulonglong2* qtp = (const ulonglong2*)(Qm + t * KPAD);
            ull a0 = 0, a1 = 0, c0 = 0, c1 = 0;
#pragma unroll
            for (int p = 0; p < 16; p++) {
                ulonglong2 kj = kjp[p];
                ulonglong2 kt = ktp[p];
                ulonglong2 qt = qtp[p];
                a0 = fma2(kt.x, kj.x, a0); a1 = fma2(kt.y, kj.y, a1);
                c0 = fma2(qt.x, kj.x, c0); c1 = fma2(qt.y, kj.y, c1);
            }
            sKK[t * 16 + j] = hsum2(add2(a0, a1));
            sQK[t * 16 + j] = hsum2(add2(c0, c1));
        }
        __syncthreads();

        // ---- region 2: gate exponentials, M / P matrices, A, E15 ----
        {
            const int t = tid >> 4, j = tid & 15;
            float e = 0.f;
            if (j <= t) {
                float gd = 0.f;
                for (int i = j + 1; i <= t; i++) gd += bg[s][i];
                e = expf(gd);
            }
            sM[t * 16 + j] = (j < t)  ? bb[s][t] * e * sKK[t * 16 + j] : 0.f;
            sP[t * 16 + j] = (j <= t) ? e * sQK[t * 16 + j] : 0.f;
            if (t == 15) sE15[j] = e;
            if (j == 0)  sA[t] = e * expf(bg[s][0]);   // A_t = exp(G_t)
        }
        __syncthreads();

        // ---- region 3: forward substitution, outputs, state update ----
        float u[16];
#pragma unroll
        for (int t = 0; t < 16; t++) {
            float acc = bb[s][t] * (Vm[t * 64 + v] - sA[t] * sKS0[t * 64 + v]);
            float s0 = 0.f, s1 = 0.f;
#pragma unroll
            for (int j = 0; j < 16; j++) {
                if (j < t) {
                    if (j & 1) s1 = fmaf(sM[t * 16 + j], u[j], s1);
                    else       s0 = fmaf(sM[t * 16 + j], u[j], s0);
                }
            }
            u[t] = acc - (s0 + s1);
        }

        // outputs: thread handles t = kh*4 + tt
#pragma unroll
        for (int tt = 0; tt < 4; tt++) {
            const int t = kh * 4 + tt;
            if (t < len) {
                float s0 = 0.f, s1 = 0.f;
#pragma unroll
                for (int j = 0; j < 16; j += 2) {
                    s0 = fmaf(sP[t * 16 + j],     u[j],     s0);
                    s1 = fmaf(sP[t * 16 + j + 1], u[j + 1], s1);
                }
                O[(size_t)(t0 + t) * VAL_DIM + h * 64 + v] =
                    fmaf(sA[t], sQS0[t * 64 + v], s0 + s1);
            }
        }

        // state update: S = A_15*S + sum_j (E15[j]*u_j) * k_j
        {
            const float aC = sA[15];
            const ull aC2 = pk2(aC, aC);
#pragma unroll
            for (int i = 0; i < 8; i++) S2[i] = mul2(aC2, S2[i]);
#pragma unroll
            for (int j = 0; j < 16; j++) {
                const float e = sE15[j] * u[j];
                const ull e2 = pk2(e, e);
                const ulonglong2* kp = (const ulonglong2*)(Km + j * KPAD + kh * 16);
                ulonglong2 k0 = kp[0], k1 = kp[1], k2 = kp[2], k3 = kp[3];
                S2[0] = fma2(k0.x, e2, S2[0]); S2[1] = fma2(k0.y, e2, S2[1]);
                S2[2] = fma2(k1.x, e2, S2[2]); S2[3] = fma2(k1.y, e2, S2[3]);
                S2[4] = fma2(k2.x, e2, S2[4]); S2[5] = fma2(k2.y, e2, S2[5]);
                S2[6] = fma2(k3.x, e2, S2[6]); S2[7] = fma2(k3.y, e2, S2[7]);
            }
        }
    }
}

// ---------------------------------------------------------------------------
// Gated RMSNorm fused with bf16 split
// ---------------------------------------------------------------------------
__global__ __launch_bounds__(512) void rmsnorm_split_kernel(
    const float* __restrict__ o, const float* __restrict__ z,
    const float* __restrict__ nw, bf16* __restrict__ onh, bf16* __restrict__ onl)
{
    const int t = blockIdx.x;
    const int w = threadIdx.x >> 5;
    const int lane = threadIdx.x & 31;
    const size_t base = (size_t)t * VAL_DIM + w * 64;

    float x0 = o[base + lane];
    float x1 = o[base + 32 + lane];
    float ss = x0 * x0 + x1 * x1;
#pragma unroll
    for (int off = 16; off; off >>= 1)
        ss += __shfl_xor_sync(0xffffffffu, ss, off);
    float r = rsqrtf(ss * (1.f / 64.f) + 1e-6f);

    float z0 = z[base + lane];
    float z1 = z[base + 32 + lane];
    float s0 = z0 / (1.f + expf(-z0));
    float s1 = z1 / (1.f + expf(-z1));

    float v0 = x0 * r * nw[lane]      * s0;
    float v1 = x1 * r * nw[lane + 32] * s1;

    bf16 h0 = __float2bfloat16(v0);
    bf16 h1 = __float2bfloat16(v1);
    onh[base + lane]      = h0;
    onh[base + 32 + lane] = h1;
    onl[base + lane]      = __float2bfloat16(v0 - __bfloat162float(h0));
    onl[base + 32 + lane] = __float2bfloat16(v1 - __bfloat162float(h1));
}

// ---------------------------------------------------------------------------
extern "C" void kernel_launch(void* const* d_in, const int* in_sizes, int n_in,
                              void* d_out, int out_size)
{
    const float* hs     = (const float*)d_in[0];
    const float* W_qkv  = (const float*)d_in[1];
    const float* W_z    = (const float*)d_in[2];
    const float* W_b    = (const float*)d_in[3];
    const float* W_a    = (const float*)d_in[4];
    const float* conv_w = (const float*)d_in[5];
    const float* dt_b   = (const float*)d_in[6];
    const float* A_log  = (const float*)d_in[7];
    const float* norm_w = (const float*)d_in[8];
    const float* W_out  = (const float*)d_in[9];
    const int*   cu     = (const int*)d_in[10];

    const int total = in_sizes[0] / HIDDEN;       // 1536
    const int B     = in_sizes[10] - 1;           // 4

    float *mixed, *qkv, *zbuf, *c3, *betab, *gateb, *obuf;
    bf16 *hs_h, *hs_l, *wqkv_h, *wqkv_l, *wz_h, *wz_l, *wba_h, *wba_l,
         *wout_h, *wout_l, *on_h, *on_l;
    cudaGetSymbolAddress((void**)&mixed,  g_mixed);
    cudaGetSymbolAddress((void**)&qkv,    g_qkv);
    cudaGetSymbolAddress((void**)&zbuf,   g_z);
    cudaGetSymbolAddress((void**)&c3,     g_c3);
    cudaGetSymbolAddress((void**)&betab,  g_beta);
    cudaGetSymbolAddress((void**)&gateb,  g_gate);
    cudaGetSymbolAddress((void**)&obuf,   g_o);
    cudaGetSymbolAddress((void**)&hs_h,   g_hs_h);
    cudaGetSymbolAddress((void**)&hs_l,   g_hs_l);
    cudaGetSymbolAddress((void**)&wqkv_h, g_wqkv_h);
    cudaGetSymbolAddress((void**)&wqkv_l, g_wqkv_l);
    cudaGetSymbolAddress((void**)&wz_h,   g_wz_h);
    cudaGetSymbolAddress((void**)&wz_l,   g_wz_l);
    cudaGetSymbolAddress((void**)&wba_h,  g_wba_h);
    cudaGetSymbolAddress((void**)&wba_l,  g_wba_l);
    cudaGetSymbolAddress((void**)&wout_h, g_wout_h);
    cudaGetSymbolAddress((void**)&wout_l, g_wout_l);
    cudaGetSymbolAddress((void**)&on_h,   g_on_h);
    cudaGetSymbolAddress((void**)&on_l,   g_on_l);

    // 0) hs split
    split4_kernel<<<(total * HIDDEN / 4 + 255) / 256, 256>>>(
        (const float4*)hs, (uint2*)hs_h, (uint2*)hs_l, total * HIDDEN / 4);
    // 1) W_qkv split
    split4_kernel<<<(CONV_DIM * HIDDEN / 4 + 255) / 256, 256>>>(
        (const float4*)W_qkv, (uint2*)wqkv_h, (uint2*)wqkv_l, CONV_DIM * HIDDEN / 4);
    // 2) W_z + W_out + W_ba splits (combined)
    split_weights2_kernel<<<(NZ4 + NO4 + NBA4 + 255) / 256, 256>>>(
        (const float4*)W_z, (const float4*)W_out, W_b, W_a,
        (uint2*)wz_h, (uint2*)wz_l, (uint2*)wout_h, (uint2*)wout_l,
        (uint2*)wba_h, (uint2*)wba_l);

    // 3) fused projections: [W_qkv | W_z | W_ba-padded] -> mixed, z, c3
    gemm_bf16split_tri<<<dim3((CONV_DIM + VAL_DIM + 128) / 128, total / 128), 256>>>(
        hs_h, hs_l, wqkv_h, wqkv_l, wz_h, wz_l, wba_h, wba_l,
        mixed, zbuf, c3, CONV_DIM, VAL_DIM, 128);

    // 4) beta / gate
    ba_finish_kernel<<<(total * 32 + 255) / 256, 256>>>(c3, dt_b, A_log, betab, gateb, total);

    // 5) fused causal conv + silu + qk norm
    conv_norm_kernel<<<total, 256>>>(mixed, conv_w, cu, B, qkv);

    // 6) chunked gated delta rule
    recurrence_chunked<<<B * HV, 256>>>(qkv, betab, gateb, cu, obuf, total);

    // 7) gated RMSNorm + split
    rmsnorm_split_kernel<<<total, 512>>>(obuf, zbuf, norm_w, on_h, on_l);

    // 8) output projection -> d_out
    gemm_bf16split_tri<<<dim3(HIDDEN / 128, total / 128), 256>>>(
        on_h, on_l, wout_h, wout_l, wout_h, wout_l, wout_h, wout_l,
        (float*)d_out, (float*)d_out, (float*)d_out, HIDDEN, 0, 0);
}